// round 6
// baseline (speedup 1.0000x reference)
#include <cuda_runtime.h>
#include <stdint.h>

// ---------------- problem constants (fixed shapes from reference) ----------------
#define RAWN   40962                    // ico-6 nodes
#define FEATN  256
#define NELEM  (RAWN * FEATN)           // 10486272 flat elements
#define NDIV   (NELEM - 1)              // linspace divisor (coprime with 256)
#define NNODES 163842                   // ico-7 nodes
#define OUTSZ  ((size_t)NNODES * FEATN) // 41943552 output floats
#define N4     (OUTSZ / 4)              // 10485888 float4s
#define NBITW  (OUTSZ / 32)             // 1310736 bitmap words

#define WARPS_PER_BLOCK 8
#define SCATTER_BLOCKS ((RAWN + WARPS_PER_BLOCK - 1) / WARPS_PER_BLOCK) // 5121
#define ZC_BLOCKS ((N4 + 255) / 256)    // 40961

// Scratch (zero-init at module load; K_zero_commit restores zeros each run so
// CUDA-graph replays are deterministic).
// g_packed[cell] = (flat_k+1)<<32 | float_bits : unsigned max == last-write-wins.
// g_bit: bit set  <=>  g_packed[cell] != 0   (both written together by winners).
__device__ unsigned long long g_packed[OUTSZ];
__device__ unsigned int       g_bit[NBITW];

// ---------------------------------------------------------------------------------
// Warp-per-source-row dedup + packed priority scatter, templated on index dtype.
// f processed in descending 32-wide rounds; first surviving write per cell-slot is
// the max-f (numpy last-write) within the row. Cross-row (and intra-row same-cell-
// different-slot) ordering resolved by the 64-bit packed atomicMax.
// ---------------------------------------------------------------------------------
template <typename IT>
__device__ __forceinline__ void scatter_row(
    int i, int lane,
    const float* __restrict__ x,
    const IT*    __restrict__ max_index,
    const IT*    __restrict__ neigh)
{
    const IT* mi = max_index + (size_t)i * FEATN;

    // Hoist all 8 per-lane max_index loads: one latency exposure instead of eight.
    int mval[8];
    #pragma unroll
    for (int j = 0; j < 8; ++j) mval[j] = (int)mi[j * 32 + lane];

    // output feature-column at f=0 for this row: floor(i*65536 / NDIV)
    const unsigned r0 = (unsigned)(((unsigned long long)i * 65536ull) / (unsigned long long)NDIV);

    unsigned taken = 0;  // warp-uniform bitmask over the 14 cell-slots

    #pragma unroll
    for (int j = 7; j >= 0; --j) {
        const int f = j * 32 + lane;                          // higher lane = higher f
        const unsigned k = (unsigned)i * 256u + (unsigned)f;  // flat index (< 2^24)
        const int m = mval[j];                                // 0..6
        unsigned r = (unsigned)(((unsigned long long)k * 256ull) / (unsigned long long)NDIV);
        if (r > 255u) r = 255u;                               // reference clamps last elem
        const int slot = m + 7 * (int)(r - r0);               // 0..13

        const unsigned peers  = __match_any_sync(0xffffffffu, slot);
        const int      leader = 31 - __clz(peers);            // max f in this round
        const bool     win    = (lane == leader) && !((taken >> slot) & 1u);
        const unsigned rslots = __reduce_or_sync(0xffffffffu, 1u << slot);

        if (win) {
            const unsigned c    = (unsigned)neigh[(size_t)i * 7 + m];
            const unsigned cell = c * 256u + r;
            const unsigned long long pk =
                ((unsigned long long)(k + 1u) << 32) |
                (unsigned long long)__float_as_uint(x[(size_t)i * FEATN + f]);
            atomicMax(&g_packed[cell], pk);                    // fire-and-forget REDG
            atomicOr(&g_bit[cell >> 5], 1u << (cell & 31u));   // flag for commit pass
        }
        taken |= rslots;
    }
}

// ---------------------------------------------------------------------------------
// K_scatter: dedup + packed scatter (index dtype auto-detected)
// ---------------------------------------------------------------------------------
__global__ void __launch_bounds__(256)
k_scatter(const float* __restrict__ x,
          const void*  __restrict__ mi_raw,
          const void*  __restrict__ ng_raw)
{
    const int warp_global = ((int)blockIdx.x * (int)blockDim.x + (int)threadIdx.x) >> 5;
    if (warp_global >= RAWN) return;
    const int lane = threadIdx.x & 31;

    // Index-dtype detection (JAX x64 disabled silently yields int32 despite jnp.int64).
    // int64 buffer: high words of first 8 neigh entries are all 0 (values < 2^31).
    // int32 buffer: those words are random node ids -- never all zero in practice.
    const uint2* probe = reinterpret_cast<const uint2*>(ng_raw);
    unsigned hiw = 0;
    #pragma unroll
    for (int t = 0; t < 8; ++t) hiw |= probe[t].y;

    if (hiw == 0)
        scatter_row<long long>(warp_global, lane, x,
                               (const long long*)mi_raw, (const long long*)ng_raw);
    else
        scatter_row<int>(warp_global, lane, x,
                         (const int*)mi_raw, (const int*)ng_raw);
}

// ---------------------------------------------------------------------------------
// K_zero_commit: stream y in order; store zeros, patching winner cells inline from
// g_packed (L2-hot from K_scatter). Resets g_bit and g_packed to zero as it goes.
// One thread per float4; 8 lanes of one warp share each bitmap word, and the clear
// (lane with idx%8==0) executes after all 8 lanes' reads in SIMT program order.
// ---------------------------------------------------------------------------------
__global__ void __launch_bounds__(256)
k_zero_commit(float* __restrict__ y)
{
    const unsigned idx = blockIdx.x * 256u + threadIdx.x;   // float4 index
    if (idx >= (unsigned)N4) return;

    const unsigned w = idx >> 3;                            // bitmap word
    const unsigned m = __ldcg(&g_bit[w]);
    float4 v = make_float4(0.f, 0.f, 0.f, 0.f);

    const unsigned nib = (m >> ((idx & 7u) * 4u)) & 0xFu;
    if (nib) {                                              // ~2.8% of threads
        const size_t cb = (size_t)idx * 4;
        if (nib & 1u) { v.x = __uint_as_float((unsigned)g_packed[cb + 0]); g_packed[cb + 0] = 0ull; }
        if (nib & 2u) { v.y = __uint_as_float((unsigned)g_packed[cb + 1]); g_packed[cb + 1] = 0ull; }
        if (nib & 4u) { v.z = __uint_as_float((unsigned)g_packed[cb + 2]); g_packed[cb + 2] = 0ull; }
        if (nib & 8u) { v.w = __uint_as_float((unsigned)g_packed[cb + 3]); g_packed[cb + 3] = 0ull; }
    }

    __stcs(&reinterpret_cast<float4*>(y)[idx], v);

    if (((idx & 7u) == 0u) && m) g_bit[w] = 0u;             // restore bitmap for replay
}

// ---------------------------------------------------------------------------------
extern "C" void kernel_launch(void* const* d_in, const int* in_sizes, int n_in,
                              void* d_out, int out_size)
{
    const float* x  = (const float*)d_in[0];
    const void*  mi = (const void*)d_in[1];   // int32 or int64, auto-detected on device
    const void*  ng = (const void*)d_in[2];
    float*       y  = (float*)d_out;

    (void)in_sizes; (void)n_in; (void)out_size;

    k_scatter<<<SCATTER_BLOCKS, 256>>>(x, mi, ng);
    k_zero_commit<<<ZC_BLOCKS, 256>>>(y);
}

// round 7
// speedup vs baseline: 2.9346x; 2.9346x over previous
#include <cuda_runtime.h>
#include <stdint.h>

// ---------------- problem constants (fixed shapes from reference) ----------------
#define RAWN   40962                    // ico-6 nodes
#define FEATN  256
#define NELEM  (RAWN * FEATN)           // 10486272 flat elements
#define NDIV   (NELEM - 1)              // linspace divisor (coprime with 256)
#define NNODES 163842                   // ico-7 nodes
#define OUTSZ  ((size_t)NNODES * FEATN) // 41943552 output floats
#define N4     (OUTSZ / 4)              // float4 count for zeroing

#define ZBLOCKS 2048                    // blocks dedicated to zeroing y inside K1
#define WARPS_PER_BLOCK 8
#define SCATTER_BLOCKS ((RAWN + WARPS_PER_BLOCK - 1) / WARPS_PER_BLOCK) // 5121
#define NSLOTS (RAWN * 14)              // <=14 winner cells (7 cols x 2 rows) per row
#define NQUADS ((NSLOTS + 3) / 4)       // K2: 4 slot entries per thread
#define K2BLOCKS ((NQUADS + 255) / 256)

// Scratch (zero-init at module load; K2 restores zeros each run so CUDA-graph
// replays are deterministic).
// g_packed[cell] = (flat_k+1)<<32 | float_bits : unsigned max == last-write-wins.
__device__ unsigned long long g_packed[OUTSZ];      // touched at ~290K cells/run
__device__ unsigned int       g_cells[NQUADS * 4];  // cell+1 per winner slot; 0 = empty

// ---------------------------------------------------------------------------------
// Warp-per-source-row dedup + packed priority scatter, templated on index dtype.
// f processed in descending 32-wide rounds; first surviving write per cell-slot is
// the max-f (numpy last-write) within the row. Cross-row ordering resolved by the
// 64-bit packed atomicMax (return unused -> fire-and-forget REDG.MAX).
// ---------------------------------------------------------------------------------
template <typename IT>
__device__ __forceinline__ void scatter_row(
    int i, int lane,
    const float* __restrict__ x,
    const IT*    __restrict__ max_index,
    const IT*    __restrict__ neigh)
{
    const IT* mi = max_index + (size_t)i * FEATN;

    // Hoist all 8 per-lane max_index loads: one latency exposure instead of eight.
    int mval[8];
    #pragma unroll
    for (int j = 0; j < 8; ++j) mval[j] = (int)mi[j * 32 + lane];

    // output feature-column at f=0 for this row: floor(i*65536 / NDIV)
    const unsigned r0 = (unsigned)(((unsigned long long)i * 65536ull) / (unsigned long long)NDIV);

    unsigned taken = 0;  // warp-uniform bitmask over the 14 cell-slots

    #pragma unroll
    for (int j = 7; j >= 0; --j) {
        const int f = j * 32 + lane;                          // higher lane = higher f
        const unsigned k = (unsigned)i * 256u + (unsigned)f;  // flat index (< 2^24)
        const int m = mval[j];                                // 0..6
        unsigned r = (unsigned)(((unsigned long long)k * 256ull) / (unsigned long long)NDIV);
        if (r > 255u) r = 255u;                               // reference clamps last elem
        const int slot = m + 7 * (int)(r - r0);               // 0..13

        const unsigned peers  = __match_any_sync(0xffffffffu, slot);
        const int      leader = 31 - __clz(peers);            // max f in this round
        const bool     win    = (lane == leader) && !((taken >> slot) & 1u);
        const unsigned rslots = __reduce_or_sync(0xffffffffu, 1u << slot);

        if (win) {
            const unsigned c    = (unsigned)neigh[(size_t)i * 7 + m];
            const unsigned cell = c * 256u + r;
            const unsigned long long pk =
                ((unsigned long long)(k + 1u) << 32) |
                (unsigned long long)__float_as_uint(x[(size_t)i * FEATN + f]);
            atomicMax(&g_packed[cell], pk);     // fire-and-forget
            g_cells[i * 14 + slot] = cell + 1u; // deterministic slot, plain store
        }
        taken |= rslots;
    }
}

// ---------------------------------------------------------------------------------
// K1: fused  (a) dedup + packed scatter   (b) zero output (pure store stream)
// Scatter blocks first in the grid: their latency-bound warps launch early and
// shadow under the bandwidth-bound zeroing stream.
// ---------------------------------------------------------------------------------
__global__ void __launch_bounds__(256)
k1_main(const float* __restrict__ x,
        const void*  __restrict__ mi_raw,
        const void*  __restrict__ ng_raw,
        float* __restrict__ y)
{
    if (blockIdx.x >= SCATTER_BLOCKS) {
        // zeroing partition: 168 MB of streaming float4 stores, no loads at all
        float4* y4 = reinterpret_cast<float4*>(y);
        const size_t stride = (size_t)ZBLOCKS * blockDim.x;
        size_t idx = (size_t)(blockIdx.x - SCATTER_BLOCKS) * blockDim.x + threadIdx.x;
        const float4 z = make_float4(0.f, 0.f, 0.f, 0.f);
        for (size_t p = idx; p < (size_t)N4; p += stride) __stcs(&y4[p], z);
        return;
    }

    const int warp_global = ((int)blockIdx.x * (int)blockDim.x + (int)threadIdx.x) >> 5;
    if (warp_global >= RAWN) return;
    const int lane = threadIdx.x & 31;

    // Index-dtype detection (JAX x64 disabled silently yields int32 despite jnp.int64).
    // int64 buffer: high words of first 8 neigh entries are all 0 (values < 2^31).
    // int32 buffer: those words are random node ids -- never all zero in practice.
    const uint2* probe = reinterpret_cast<const uint2*>(ng_raw);
    unsigned hiw = 0;
    #pragma unroll
    for (int t = 0; t < 8; ++t) hiw |= probe[t].y;

    if (hiw == 0)
        scatter_row<long long>(warp_global, lane, x,
                               (const long long*)mi_raw, (const long long*)ng_raw);
    else
        scatter_row<int>(warp_global, lane, x,
                         (const int*)mi_raw, (const int*)ng_raw);
}

// ---------------------------------------------------------------------------------
// K2: commit winners and restore scratch to zero. No atomics: duplicate entries
// for one cell either both read the full packed value (both store the SAME y value
// -- benign) or the later reads 0 post-reset and skips. 4 entries/thread for MLP.
// ---------------------------------------------------------------------------------
__global__ void __launch_bounds__(256)
k2_commit(float* __restrict__ y)
{
    const unsigned q = blockIdx.x * 256u + threadIdx.x;
    if (q >= (unsigned)NQUADS) return;

    const uint4 e = reinterpret_cast<const uint4*>(g_cells)[q];
    unsigned c[4] = { e.x, e.y, e.z, e.w };

    // Phase 1: issue all scattered loads (independent -> MLP=4)
    unsigned long long p[4];
    #pragma unroll
    for (int t = 0; t < 4; ++t)
        p[t] = c[t] ? g_packed[c[t] - 1u] : 0ull;

    // Phase 2: dependent stores
    #pragma unroll
    for (int t = 0; t < 4; ++t) {
        if (c[t] && p[t]) {
            y[c[t] - 1u] = __uint_as_float((unsigned)(p[t] & 0xffffffffull));
            g_packed[c[t] - 1u] = 0ull;         // restore sentinel for replay
        }
    }

    if (e.x | e.y | e.z | e.w)
        reinterpret_cast<uint4*>(g_cells)[q] = make_uint4(0u, 0u, 0u, 0u);
}

// ---------------------------------------------------------------------------------
extern "C" void kernel_launch(void* const* d_in, const int* in_sizes, int n_in,
                              void* d_out, int out_size)
{
    const float* x  = (const float*)d_in[0];
    const void*  mi = (const void*)d_in[1];   // int32 or int64, auto-detected on device
    const void*  ng = (const void*)d_in[2];
    float*       y  = (float*)d_out;

    (void)in_sizes; (void)n_in; (void)out_size;

    k1_main<<<SCATTER_BLOCKS + ZBLOCKS, 256>>>(x, mi, ng, y);
    k2_commit<<<K2BLOCKS, 256>>>(y);
}